// round 5
// baseline (speedup 1.0000x reference)
#include <cuda_runtime.h>
#include <math.h>

// ---------------------------------------------------------------------------
// DCWTv2InferenceCache: segment-tree cover-set attention decode step.
// Single fused persistent kernel:
//   blocks [nAttn, GRID_F): balanced HBM stream of big-node chunk partial
//                           means -> atomicAdd into g_f; then count g_done.
//   blocks [0, nAttn):      attention for (src, head). Independent work
//                           (q proj, local window, small nodes) runs
//                           immediately (overlapped with the stream); big-node
//                           blocks spin on g_done before reading g_f (L2).
// Residency proof: 608 blocks, launch_bounds(256,4), smem ~21KB/block
//                  -> >=4 blocks/SM * 152 SMs = all blocks co-resident.
// ---------------------------------------------------------------------------

#define TOKDIM   1024            // 16 heads * 64 dims
#define HEADS    16
#define HDIM     64
#define MAXBIG   16
#define MAXNODES 40
#define GRID_F   608             // 152 SMs * 4 blocks

__device__ float g_f[(size_t)MAXBIG * 64 * TOKDIM];
__device__ int   g_done;

struct PartParams {
    int  nBig;
    int  a[MAXBIG];              // token offset of node
    int  C[MAXBIG];              // chunks (of 64 tokens) in node
    float inv[MAXBIG];           // 1/C
    long unitBase[MAXBIG + 1];   // prefix of C[n]*64 units
};

struct AttnParams {
    int n;                       // number of cover nodes
    float inv_n;                 // 1/n
    int depth[MAXNODES];
    int K[MAXNODES];             // min(L, 64)
    int isBig[MAXNODES];         // 1 -> g_f slot off[], 0 -> v_tokens token off[]
    int off[MAXNODES];
};

__global__ void __launch_bounds__(256, 4) fused_kernel(
    const float* __restrict__ V,
    const float* __restrict__ q,
    const float* __restrict__ W,
    const float* __restrict__ temp,
    PartParams bp, AttnParams ap, int pos, long U,
    float* __restrict__ out)
{
    const int b    = blockIdx.x;
    const int tid  = threadIdx.x;
    const int nAttn = (ap.n + 1) * HEADS;
    const int NS    = GRID_F - nAttn;

    // ======================= streaming blocks =======================
    if (b >= nAttn) {
        long u  = (long)(b - nAttn)     * U / NS;
        long u1 = (long)(b - nAttn + 1) * U / NS;

        while (u < u1) {
            int n = 0;
            while (u >= bp.unitBase[n + 1]) n++;
            long rem = u - bp.unitBase[n];
            int  k   = (int)(rem / bp.C[n]);
            int  c   = (int)(rem % bp.C[n]);
            long run = bp.C[n] - c;
            if (run > u1 - u) run = u1 - u;

            const float4* p = (const float4*)(V + ((long)bp.a[n] + (long)c * 64 + k) * TOKDIM) + tid;
            const long STR = 64L * TOKDIM / 4;

            float4 a0 = {0,0,0,0}, a1 = {0,0,0,0}, a2 = {0,0,0,0}, a3 = {0,0,0,0};
            long r = 0;
            for (; r + 8 <= run; r += 8) {
                float4 x0 = p[0];
                float4 x1 = p[STR];
                float4 x2 = p[2 * STR];
                float4 x3 = p[3 * STR];
                float4 x4 = p[4 * STR];
                float4 x5 = p[5 * STR];
                float4 x6 = p[6 * STR];
                float4 x7 = p[7 * STR];
                a0.x += x0.x; a0.y += x0.y; a0.z += x0.z; a0.w += x0.w;
                a1.x += x1.x; a1.y += x1.y; a1.z += x1.z; a1.w += x1.w;
                a2.x += x2.x; a2.y += x2.y; a2.z += x2.z; a2.w += x2.w;
                a3.x += x3.x; a3.y += x3.y; a3.z += x3.z; a3.w += x3.w;
                a0.x += x4.x; a0.y += x4.y; a0.z += x4.z; a0.w += x4.w;
                a1.x += x5.x; a1.y += x5.y; a1.z += x5.z; a1.w += x5.w;
                a2.x += x6.x; a2.y += x6.y; a2.z += x6.z; a2.w += x6.w;
                a3.x += x7.x; a3.y += x7.y; a3.z += x7.z; a3.w += x7.w;
                p += 8 * STR;
            }
            for (; r < run; r++) {
                float4 x0 = p[0];
                a0.x += x0.x; a0.y += x0.y; a0.z += x0.z; a0.w += x0.w;
                p += STR;
            }
            float s = bp.inv[n];
            float* o = g_f + ((long)n * 64 + k) * TOKDIM + tid * 4;
            atomicAdd(o + 0, ((a0.x + a1.x) + (a2.x + a3.x)) * s);
            atomicAdd(o + 1, ((a0.y + a1.y) + (a2.y + a3.y)) * s);
            atomicAdd(o + 2, ((a0.z + a1.z) + (a2.z + a3.z)) * s);
            atomicAdd(o + 3, ((a0.w + a1.w) + (a2.w + a3.w)) * s);
            u += run;
        }
        __threadfence();
        __syncthreads();
        if (tid == 0) atomicAdd(&g_done, 1);
        return;
    }

    // ======================= attention blocks =======================
    const int src = b / HEADS;
    const int h   = b % HEADS;

    __shared__ float f_sh[64 * 65];     // node f tile, padded
    __shared__ float s_sh[512];
    __shared__ float red[256];
    __shared__ float q_sh[HDIM];
    __shared__ float qd[HDIM];
    __shared__ float s_scale, s_mx, s_sum;

    if (tid < HDIM) q_sh[tid] = q[h * HDIM + tid];
    __syncthreads();

    if (src < ap.n) {
        // ---------------- cover-set node attention ----------------
        const int depth = ap.depth[src];
        const int K     = ap.K[src];

        // qd = q + q @ W^T : 256 threads, d=tid&63, 4 e-groups of 16
        {
            const float* Wd = W + (long)depth * HDIM * HDIM;
            int d = tid & 63, g = tid >> 6;
            float acc = 0.f;
            #pragma unroll
            for (int e = g * 16; e < g * 16 + 16; e++)
                acc += q_sh[e] * Wd[d * HDIM + e];
            red[tid] = acc;
        }
        if (tid == 0) {
            float t  = temp[depth];
            float sp = log1pf(expf(t));               // softplus
            s_scale  = 1.0f / ((sp + 1e-6f) * 8.0f);  // sqrt(64)=8
        }
        __syncthreads();
        if (tid < HDIM)
            qd[tid] = q_sh[tid] + ((red[tid] + red[64 + tid]) + (red[128 + tid] + red[192 + tid]));

        // big nodes: wait for the stream to finish before reading g_f
        const float* fsrc;
        if (ap.isBig[src]) {
            if (tid == 0) {
                while (atomicAdd(&g_done, 0) < NS) __nanosleep(256);
            }
            __syncthreads();
            __threadfence();
            fsrc = g_f + (long)ap.off[src] * 64 * TOKDIM;
        } else {
            fsrc = V + (long)ap.off[src] * TOKDIM;
            __syncthreads();
        }

        // load f tile [K,64] coalesced
        for (int i = tid; i < K * HDIM; i += 256) {
            int k = i >> 6, d = i & 63;
            f_sh[k * 65 + d] = fsrc[(long)k * TOKDIM + h * HDIM + d];
        }
        __syncthreads();

        // scores
        float sc = -1e30f;
        if (tid < K) {
            float acc = 0.f;
            #pragma unroll
            for (int d = 0; d < HDIM; d++) acc += qd[d] * f_sh[tid * 65 + d];
            sc = acc * s_scale;
        }
        if (tid < 64) red[tid] = sc;
        __syncthreads();
        if (tid < 32) {
            float m = fmaxf(red[tid], red[tid + 32]);
            #pragma unroll
            for (int o = 16; o > 0; o >>= 1)
                m = fmaxf(m, __shfl_xor_sync(0xffffffff, m, o));
            if (tid == 0) s_mx = m;
        }
        __syncthreads();

        float e = (tid < K) ? expf(sc - s_mx) : 0.f;
        if (tid < 64) { s_sh[tid] = e; red[tid] = e; }
        __syncthreads();
        if (tid < 32) {
            float sm = red[tid] + red[tid + 32];
            #pragma unroll
            for (int o = 16; o > 0; o >>= 1)
                sm += __shfl_xor_sync(0xffffffff, sm, o);
            if (tid == 0) s_sum = sm;
        }
        __syncthreads();

        // weighted sum: 4 k-groups x 64 dims
        {
            int g = tid >> 6, d = tid & 63;
            float acc = 0.f;
            for (int k = g; k < K; k += 4) acc += s_sh[k] * f_sh[k * 65 + d];
            red[tid] = acc;
        }
        __syncthreads();
        if (tid < HDIM) {
            float o = (red[tid] + red[64 + tid]) + (red[128 + tid] + red[192 + tid]);
            atomicAdd(out + h * HDIM + tid, (o / s_sum) * ap.inv_n);
        }
    } else {
        // ---------------- local-window attention ----------------
        const int nloc = pos < 512 ? pos : 512;
        const int base = pos - nloc;

        s_sh[tid] = -1e30f;
        s_sh[tid + 256] = -1e30f;
        // per-thread scores (2 tokens per thread), direct gmem, high MLP
        for (int t = tid; t < nloc; t += 256) {
            const float4* vp = (const float4*)(V + (long)(base + t) * TOKDIM + h * HDIM);
            const float4* qp = (const float4*)q_sh;
            float acc = 0.f;
            #pragma unroll
            for (int i = 0; i < 16; i++) {
                float4 x = vp[i];
                float4 qq = qp[i];
                acc += x.x * qq.x + x.y * qq.y + x.z * qq.z + x.w * qq.w;
            }
            s_sh[t] = acc * 0.125f;            // 1/sqrt(64)
        }
        __syncthreads();

        // max over 512
        red[tid] = fmaxf(s_sh[tid], s_sh[tid + 256]);
        __syncthreads();
        #pragma unroll
        for (int st = 128; st >= 32; st >>= 1) {
            if (tid < st) red[tid] = fmaxf(red[tid], red[tid + st]);
            __syncthreads();
        }
        if (tid < 32) {
            float m = red[tid];
            #pragma unroll
            for (int o = 16; o > 0; o >>= 1)
                m = fmaxf(m, __shfl_xor_sync(0xffffffff, m, o));
            if (tid == 0) s_mx = m;
        }
        __syncthreads();

        // exp + sum
        float lsum = 0.f;
        for (int t = tid; t < 512; t += 256) {
            float e = (t < nloc) ? expf(s_sh[t] - s_mx) : 0.f;
            s_sh[t] = e;
            lsum += e;
        }
        red[tid] = lsum;
        __syncthreads();
        #pragma unroll
        for (int st = 128; st >= 32; st >>= 1) {
            if (tid < st) red[tid] += red[tid + st];
            __syncthreads();
        }
        if (tid < 32) {
            float sm = red[tid];
            #pragma unroll
            for (int o = 16; o > 0; o >>= 1)
                sm += __shfl_xor_sync(0xffffffff, sm, o);
            if (tid == 0) s_sum = sm;
        }
        __syncthreads();

        // weighted sum: 4 k-groups x 64 dims, coalesced reads of V
        {
            int g = tid >> 6, d = tid & 63;
            float acc = 0.f;
            for (int k = g; k < nloc; k += 4)
                acc += s_sh[k] * V[(long)(base + k) * TOKDIM + h * HDIM + d];
            red[tid] = acc;
        }
        __syncthreads();
        if (tid < HDIM) {
            float o = (red[tid] + red[64 + tid]) + (red[128 + tid] + red[192 + tid]);
            atomicAdd(out + h * HDIM + tid, (s_sum > 0.f) ? (o / s_sum) : 0.f);
        }
    }
}

// ---------------------------------------------------------------------------
extern "C" void kernel_launch(void* const* d_in, const int* in_sizes, int n_in,
                              void* d_out, int out_size)
{
    const float* V    = (const float*)d_in[0];
    const float* q    = (const float*)d_in[1];
    const float* W    = (const float*)d_in[2];
    const float* temp = (const float*)d_in[3];

    const int pos = in_sizes[0] / TOKDIM;

    const int  LOG_N      = 17;
    const long LEAF_START = 1L << LOG_N;
    const long MAX_LEN    = 65536;

    PartParams bp;  bp.nBig = 0;
    AttnParams ap;  ap.n = 0;

    auto addNode = [&](long idx) {
        int fl = 0; long t = idx;
        while (t > 1) { t >>= 1; fl++; }
        int depth = LOG_N - fl;
        long L = 1L << depth;
        long a = (idx << depth) - LEAF_START;
        int ni = ap.n++;
        ap.depth[ni] = depth;
        ap.K[ni] = (int)(L < 64 ? L : 64);
        if (L > 64) {
            int bi = bp.nBig++;
            bp.a[bi]   = (int)a;
            bp.C[bi]   = (int)(L / 64);
            bp.inv[bi] = 1.0f / (float)(L / 64);
            ap.isBig[ni] = 1;
            ap.off[ni]   = bi;
        } else {
            ap.isBig[ni] = 0;
            ap.off[ni]   = (int)a;
        }
    };

    long l = LEAF_START;
    long r = LEAF_START + (pos < MAX_LEN ? (long)pos : MAX_LEN);
    while (l < r) {
        if (l & 1) { addNode(l); l++; }
        if (r & 1) { r--; addNode(r); }
        l >>= 1; r >>= 1;
    }
    ap.inv_n = ap.n > 0 ? 1.0f / (float)ap.n : 0.f;

    bp.unitBase[0] = 0;
    for (int i = 0; i < bp.nBig; i++)
        bp.unitBase[i + 1] = bp.unitBase[i] + (long)bp.C[i] * 64;
    long U = bp.nBig ? bp.unitBase[bp.nBig] : 0;

    cudaMemsetAsync(d_out, 0, (size_t)out_size * sizeof(float));
    void* ctr_ptr = nullptr;
    cudaGetSymbolAddress(&ctr_ptr, g_done);
    cudaMemsetAsync(ctr_ptr, 0, sizeof(int));
    if (bp.nBig > 0) {
        void* gf_ptr = nullptr;
        cudaGetSymbolAddress(&gf_ptr, g_f);
        cudaMemsetAsync(gf_ptr, 0, (size_t)bp.nBig * 64 * TOKDIM * sizeof(float));
    }
    fused_kernel<<<GRID_F, 256>>>(V, q, W, temp, bp, ap, pos, U, (float*)d_out);
}

// round 6
// speedup vs baseline: 1.0827x; 1.0827x over previous
#include <cuda_runtime.h>
#include <math.h>

// ---------------------------------------------------------------------------
// DCWTv2InferenceCache: segment-tree cover-set attention decode step.
// Single fused kernel, all blocks co-resident (912 = 152 SMs * 6 via
// launch_bounds(256,6)):
//   blocks [nAttn, 912): balanced HBM stream of big-node chunk partial means
//                        -> atomicAdd into g_f; fence; count g_done.
//   blocks [0, nAttn):   attention for (src, head). Independent work (q proj,
//                        local window, small nodes) runs immediately,
//                        overlapped with the stream, with ALL gmem accesses
//                        coalesced (polite to shared L1tex queues); big-node
//                        blocks poll g_done (volatile) then read g_f from L2.
// ---------------------------------------------------------------------------

#define TOKDIM   1024            // 16 heads * 64 dims
#define HEADS    16
#define HDIM     64
#define MAXBIG   16
#define MAXNODES 40
#define GRID_F   912             // 152 SMs * 6 blocks

__device__ float g_f[(size_t)MAXBIG * 64 * TOKDIM];
__device__ int   g_done;

struct PartParams {
    int  nBig;
    int  a[MAXBIG];              // token offset of node
    int  C[MAXBIG];              // chunks (of 64 tokens) in node
    float inv[MAXBIG];           // 1/C
    long unitBase[MAXBIG + 1];   // prefix of C[n]*64 units
};

struct AttnParams {
    int n;                       // number of cover nodes
    float inv_n;                 // 1/n
    int depth[MAXNODES];
    int K[MAXNODES];             // min(L, 64)
    int isBig[MAXNODES];         // 1 -> g_f slot off[], 0 -> v_tokens token off[]
    int off[MAXNODES];
};

__global__ void __launch_bounds__(256, 6) fused_kernel(
    const float* __restrict__ V,
    const float* __restrict__ q,
    const float* __restrict__ W,
    const float* __restrict__ temp,
    PartParams bp, AttnParams ap, int pos, long U,
    float* __restrict__ out)
{
    const int b     = blockIdx.x;
    const int tid   = threadIdx.x;
    const int nAttn = (ap.n + 1) * HEADS;
    const int NS    = GRID_F - nAttn;

    __shared__ float fW[64 * 65];       // shared buffer: W (transposed) then f tile / token tile
    __shared__ float s_sh[512];
    __shared__ float red[256];
    __shared__ float q_sh[HDIM];
    __shared__ float qd[HDIM];
    __shared__ float s_scale, s_mx, s_sum;

    // ======================= streaming blocks =======================
    if (b >= nAttn) {
        long u  = (long)(b - nAttn)     * U / NS;
        long u1 = (long)(b - nAttn + 1) * U / NS;

        while (u < u1) {
            int n = 0;
            while (u >= bp.unitBase[n + 1]) n++;
            long rem = u - bp.unitBase[n];
            int  k   = (int)(rem / bp.C[n]);
            int  c   = (int)(rem % bp.C[n]);
            long run = bp.C[n] - c;
            if (run > u1 - u) run = u1 - u;

            const float4* p = (const float4*)(V + ((long)bp.a[n] + (long)c * 64 + k) * TOKDIM) + tid;
            const long STR = 64L * TOKDIM / 4;

            float4 a0 = {0,0,0,0}, a1 = {0,0,0,0};
            long r = 0;
            for (; r + 4 <= run; r += 4) {
                float4 x0 = p[0];
                float4 x1 = p[STR];
                float4 x2 = p[2 * STR];
                float4 x3 = p[3 * STR];
                a0.x += x0.x; a0.y += x0.y; a0.z += x0.z; a0.w += x0.w;
                a1.x += x1.x; a1.y += x1.y; a1.z += x1.z; a1.w += x1.w;
                a0.x += x2.x; a0.y += x2.y; a0.z += x2.z; a0.w += x2.w;
                a1.x += x3.x; a1.y += x3.y; a1.z += x3.z; a1.w += x3.w;
                p += 4 * STR;
            }
            for (; r < run; r++) {
                float4 x0 = p[0];
                a0.x += x0.x; a0.y += x0.y; a0.z += x0.z; a0.w += x0.w;
                p += STR;
            }
            float s = bp.inv[n];
            float* o = g_f + ((long)n * 64 + k) * TOKDIM + tid * 4;
            atomicAdd(o + 0, (a0.x + a1.x) * s);
            atomicAdd(o + 1, (a0.y + a1.y) * s);
            atomicAdd(o + 2, (a0.z + a1.z) * s);
            atomicAdd(o + 3, (a0.w + a1.w) * s);
            u += run;
        }
        __threadfence();
        __syncthreads();
        if (tid == 0) atomicAdd(&g_done, 1);
        return;
    }

    // ======================= attention blocks =======================
    const int src = b / HEADS;
    const int h   = b % HEADS;

    if (tid < HDIM) q_sh[tid] = q[h * HDIM + tid];
    __syncthreads();

    if (src < ap.n) {
        // ---------------- cover-set node attention ----------------
        const int depth = ap.depth[src];
        const int K     = ap.K[src];

        // stage W[depth] coalesced -> fW transposed (fW[e*65+d] = W[d][e])
        const float* Wd = W + (long)depth * HDIM * HDIM;
        #pragma unroll
        for (int i = tid; i < HDIM * HDIM; i += 256) {
            int d = i >> 6, e = i & 63;
            fW[e * 65 + d] = Wd[i];
        }
        if (tid == 0) {
            float t  = temp[depth];
            float sp = log1pf(expf(t));               // softplus
            s_scale  = 1.0f / ((sp + 1e-6f) * 8.0f);  // sqrt(64)=8
        }
        __syncthreads();

        // qd = q + q @ W^T from smem (conflict-free)
        if (tid < HDIM) {
            float acc = q_sh[tid];
            #pragma unroll
            for (int e = 0; e < HDIM; e++) acc += q_sh[e] * fW[e * 65 + tid];
            qd[tid] = acc;
        }
        __syncthreads();   // qd done, fW free for reuse

        // big nodes: wait for the stream before reading g_f
        const float* fsrc;
        if (ap.isBig[src]) {
            if (tid == 0) {
                volatile int* dp = &g_done;
                while (*dp < NS) __nanosleep(512);
            }
            __syncthreads();
            __threadfence();
            fsrc = g_f + (long)ap.off[src] * 64 * TOKDIM;
        } else {
            fsrc = V + (long)ap.off[src] * TOKDIM;
        }

        // load f tile [K,64] coalesced into fW
        for (int i = tid; i < K * HDIM; i += 256) {
            int k = i >> 6, d = i & 63;
            fW[k * 65 + d] = fsrc[(long)k * TOKDIM + h * HDIM + d];
        }
        __syncthreads();

        // scores
        float sc = -1e30f;
        if (tid < K) {
            float acc = 0.f;
            #pragma unroll
            for (int d = 0; d < HDIM; d++) acc += qd[d] * fW[tid * 65 + d];
            sc = acc * s_scale;
        }
        if (tid < 64) red[tid] = sc;
        __syncthreads();
        if (tid < 32) {
            float m = fmaxf(red[tid], red[tid + 32]);
            #pragma unroll
            for (int o = 16; o > 0; o >>= 1)
                m = fmaxf(m, __shfl_xor_sync(0xffffffff, m, o));
            if (tid == 0) s_mx = m;
        }
        __syncthreads();

        float e = (tid < K) ? expf(sc - s_mx) : 0.f;
        if (tid < 64) { s_sh[tid] = e; red[tid] = e; }
        __syncthreads();
        if (tid < 32) {
            float sm = red[tid] + red[tid + 32];
            #pragma unroll
            for (int o = 16; o > 0; o >>= 1)
                sm += __shfl_xor_sync(0xffffffff, sm, o);
            if (tid == 0) s_sum = sm;
        }
        __syncthreads();

        // weighted sum: 4 k-groups x 64 dims
        {
            int g = tid >> 6, d = tid & 63;
            float acc = 0.f;
            for (int k = g; k < K; k += 4) acc += s_sh[k] * fW[k * 65 + d];
            red[tid] = acc;
        }
        __syncthreads();
        if (tid < HDIM) {
            float o = (red[tid] + red[64 + tid]) + (red[128 + tid] + red[192 + tid]);
            atomicAdd(out + h * HDIM + tid, (o / s_sum) * ap.inv_n);
        }
    } else {
        // ---------------- local-window attention ----------------
        const int nloc = pos < 512 ? pos : 512;
        const int base = pos - nloc;

        s_sh[tid]       = -1e30f;
        s_sh[tid + 256] = -1e30f;
        __syncthreads();

        // scores: 64-token chunks staged through smem (coalesced; latency
        // hidden under the concurrent HBM stream)
        const int nch = (nloc + 63) >> 6;
        for (int cc = 0; cc < nch; cc++) {
            int t0  = cc << 6;
            int cnt = nloc - t0; if (cnt > 64) cnt = 64;
            for (int i = tid; i < cnt * 64; i += 256) {
                int k = i >> 6, d = i & 63;
                fW[k * 65 + d] = V[(long)(base + t0 + k) * TOKDIM + h * HDIM + d];
            }
            __syncthreads();
            if (tid < cnt) {
                float acc = 0.f;
                #pragma unroll
                for (int d = 0; d < HDIM; d++) acc += q_sh[d] * fW[tid * 65 + d];
                s_sh[t0 + tid] = acc * 0.125f;        // 1/sqrt(64)
            }
            __syncthreads();
        }

        // max over 512
        red[tid] = fmaxf(s_sh[tid], s_sh[tid + 256]);
        __syncthreads();
        #pragma unroll
        for (int st = 128; st >= 32; st >>= 1) {
            if (tid < st) red[tid] = fmaxf(red[tid], red[tid + st]);
            __syncthreads();
        }
        if (tid < 32) {
            float m = red[tid];
            #pragma unroll
            for (int o = 16; o > 0; o >>= 1)
                m = fmaxf(m, __shfl_xor_sync(0xffffffff, m, o));
            if (tid == 0) s_mx = m;
        }
        __syncthreads();

        // exp + sum
        float lsum = 0.f;
        for (int t = tid; t < 512; t += 256) {
            float e = (t < nloc) ? expf(s_sh[t] - s_mx) : 0.f;
            s_sh[t] = e;
            lsum += e;
        }
        red[tid] = lsum;
        __syncthreads();
        #pragma unroll
        for (int st = 128; st >= 32; st >>= 1) {
            if (tid < st) red[tid] += red[tid + st];
            __syncthreads();
        }
        if (tid < 32) {
            float sm = red[tid];
            #pragma unroll
            for (int o = 16; o > 0; o >>= 1)
                sm += __shfl_xor_sync(0xffffffff, sm, o);
            if (tid == 0) s_sum = sm;
        }
        __syncthreads();

        // weighted sum: 4 k-groups x 64 dims, coalesced (1 line / warp-LDG)
        {
            int g = tid >> 6, d = tid & 63;
            float acc = 0.f;
            for (int k = g; k < nloc; k += 4)
                acc += s_sh[k] * V[(long)(base + k) * TOKDIM + h * HDIM + d];
            red[tid] = acc;
        }
        __syncthreads();
        if (tid < HDIM) {
            float o = (red[tid] + red[64 + tid]) + (red[128 + tid] + red[192 + tid]);
            atomicAdd(out + h * HDIM + tid, (s_sum > 0.f) ? (o / s_sum) : 0.f);
        }
    }
}

// ---------------------------------------------------------------------------
extern "C" void kernel_launch(void* const* d_in, const int* in_sizes, int n_in,
                              void* d_out, int out_size)
{
    const float* V    = (const float*)d_in[0];
    const float* q    = (const float*)d_in[1];
    const float* W    = (const float*)d_in[2];
    const float* temp = (const float*)d_in[3];

    const int pos = in_sizes[0] / TOKDIM;

    const int  LOG_N      = 17;
    const long LEAF_START = 1L << LOG_N;
    const long MAX_LEN    = 65536;

    PartParams bp;  bp.nBig = 0;
    AttnParams ap;  ap.n = 0;

    auto addNode = [&](long idx) {
        int fl = 0; long t = idx;
        while (t > 1) { t >>= 1; fl++; }
        int depth = LOG_N - fl;
        long L = 1L << depth;
        long a = (idx << depth) - LEAF_START;
        int ni = ap.n++;
        ap.depth[ni] = depth;
        ap.K[ni] = (int)(L < 64 ? L : 64);
        if (L > 64) {
            int bi = bp.nBig++;
            bp.a[bi]   = (int)a;
            bp.C[bi]   = (int)(L / 64);
            bp.inv[bi] = 1.0f / (float)(L / 64);
            ap.isBig[ni] = 1;
            ap.off[ni]   = bi;
        } else {
            ap.isBig[ni] = 0;
            ap.off[ni]   = (int)a;
        }
    };

    long l = LEAF_START;
    long r = LEAF_START + (pos < MAX_LEN ? (long)pos : MAX_LEN);
    while (l < r) {
        if (l & 1) { addNode(l); l++; }
        if (r & 1) { r--; addNode(r); }
        l >>= 1; r >>= 1;
    }
    ap.inv_n = ap.n > 0 ? 1.0f / (float)ap.n : 0.f;

    bp.unitBase[0] = 0;
    for (int i = 0; i < bp.nBig; i++)
        bp.unitBase[i + 1] = bp.unitBase[i] + (long)bp.C[i] * 64;
    long U = bp.nBig ? bp.unitBase[bp.nBig] : 0;

    cudaMemsetAsync(d_out, 0, (size_t)out_size * sizeof(float));
    void* ctr_ptr = nullptr;
    cudaGetSymbolAddress(&ctr_ptr, g_done);
    cudaMemsetAsync(ctr_ptr, 0, sizeof(int));
    if (bp.nBig > 0) {
        void* gf_ptr = nullptr;
        cudaGetSymbolAddress(&gf_ptr, g_f);
        cudaMemsetAsync(gf_ptr, 0, (size_t)bp.nBig * 64 * TOKDIM * sizeof(float));
    }
    fused_kernel<<<GRID_F, 256>>>(V, q, W, temp, bp, ap, pos, U, (float*)d_out);
}

// round 7
// speedup vs baseline: 1.1045x; 1.0201x over previous
#include <cuda_runtime.h>
#include <math.h>

// ---------------------------------------------------------------------------
// DCWTv2InferenceCache: segment-tree cover-set attention decode step.
// Graph fork/join:
//   main stream: memset g_f -> partial_kernel (full-residency HBM stream,
//                1216 blocks @ 5.5 TB/s) -> [join] -> big_kernel (L2-only).
//   side stream: memset d_out -> indep_kernel (local window + small nodes +
//                qd/scale precompute for big nodes), concurrent with stream.
// ---------------------------------------------------------------------------

#define TOKDIM   1024            // 16 heads * 64 dims
#define HEADS    16
#define HDIM     64
#define MAXBIG   16
#define MAXNODES 40
#define GRID_P   1216            // 152 SMs * 8 blocks (256 thr)

__device__ float g_f[(size_t)MAXBIG * 64 * TOKDIM];
__device__ float g_qd[MAXBIG * HEADS * HDIM];
__device__ float g_scale[MAXBIG];

struct PartParams {
    int  nBig;
    int  a[MAXBIG];              // token offset of node
    int  C[MAXBIG];              // chunks (of 64 tokens) in node
    float inv[MAXBIG];           // 1/C
    long unitBase[MAXBIG + 1];   // prefix of C[n]*64 units
};

struct IndepParams {
    int   nSmall;
    int   sdepth[MAXNODES];
    int   sK[MAXNODES];
    int   soff[MAXNODES];        // token offset in V
    int   nBig;
    int   bdepth[MAXBIG];
    float inv_n;
};

// ---- partial: balanced chunk means -> red into g_f (R2 proven config) ------
__global__ void __launch_bounds__(256) partial_kernel(
    const float* __restrict__ V, PartParams P, long U)
{
    const int tid = threadIdx.x;
    long u  = (long)blockIdx.x       * U / GRID_P;
    long u1 = ((long)blockIdx.x + 1) * U / GRID_P;

    while (u < u1) {
        int n = 0;
        while (u >= P.unitBase[n + 1]) n++;
        long rem = u - P.unitBase[n];
        int  k   = (int)(rem / P.C[n]);
        int  c   = (int)(rem % P.C[n]);
        long run = P.C[n] - c;
        if (run > u1 - u) run = u1 - u;

        const float4* p = (const float4*)(V + ((long)P.a[n] + (long)c * 64 + k) * TOKDIM) + tid;
        const long STR = 64L * TOKDIM / 4;

        float4 a0 = {0,0,0,0}, a1 = {0,0,0,0}, a2 = {0,0,0,0}, a3 = {0,0,0,0};
        long r = 0;
        for (; r + 8 <= run; r += 8) {
            float4 x0 = p[0];
            float4 x1 = p[STR];
            float4 x2 = p[2 * STR];
            float4 x3 = p[3 * STR];
            float4 x4 = p[4 * STR];
            float4 x5 = p[5 * STR];
            float4 x6 = p[6 * STR];
            float4 x7 = p[7 * STR];
            a0.x += x0.x; a0.y += x0.y; a0.z += x0.z; a0.w += x0.w;
            a1.x += x1.x; a1.y += x1.y; a1.z += x1.z; a1.w += x1.w;
            a2.x += x2.x; a2.y += x2.y; a2.z += x2.z; a2.w += x2.w;
            a3.x += x3.x; a3.y += x3.y; a3.z += x3.z; a3.w += x3.w;
            a0.x += x4.x; a0.y += x4.y; a0.z += x4.z; a0.w += x4.w;
            a1.x += x5.x; a1.y += x5.y; a1.z += x5.z; a1.w += x5.w;
            a2.x += x6.x; a2.y += x6.y; a2.z += x6.z; a2.w += x6.w;
            a3.x += x7.x; a3.y += x7.y; a3.z += x7.z; a3.w += x7.w;
            p += 8 * STR;
        }
        for (; r < run; r++) {
            float4 x0 = p[0];
            a0.x += x0.x; a0.y += x0.y; a0.z += x0.z; a0.w += x0.w;
            p += STR;
        }
        float s = P.inv[n];
        float* o = g_f + ((long)n * 64 + k) * TOKDIM + tid * 4;
        atomicAdd(o + 0, ((a0.x + a1.x) + (a2.x + a3.x)) * s);
        atomicAdd(o + 1, ((a0.y + a1.y) + (a2.y + a3.y)) * s);
        atomicAdd(o + 2, ((a0.z + a1.z) + (a2.z + a3.z)) * s);
        atomicAdd(o + 3, ((a0.w + a1.w) + (a2.w + a3.w)) * s);
        u += run;
    }
}

// ---- indep: local window + small nodes + big-node qd/scale prep ------------
// grid.x = 16 (local) + nSmall*16 + nBig ; block = 512.
__global__ void __launch_bounds__(512) indep_kernel(
    const float* __restrict__ V,
    const float* __restrict__ q,
    const float* __restrict__ W,
    const float* __restrict__ temp,
    IndepParams P, int pos, float* __restrict__ out)
{
    const int b   = blockIdx.x;
    const int tid = threadIdx.x;

    __shared__ float fW[64 * 65];
    __shared__ float s_sh[512];
    __shared__ float red[512];
    __shared__ float q_sh[HEADS * HDIM];   // full q for prep; [0..63] used otherwise
    __shared__ float qd[HDIM];
    __shared__ float s_scale, s_mx, s_sum;

    if (b < HEADS) {
        // ================= local-window attention =================
        const int h    = b;
        const int nloc = pos < 512 ? pos : 512;
        const int base = pos - nloc;

        if (tid < HDIM) q_sh[tid] = q[h * HDIM + tid];
        __syncthreads();

        float sc = -1e30f;
        if (tid < nloc) {
            const float4* vp = (const float4*)(V + (long)(base + tid) * TOKDIM + h * HDIM);
            const float4* qp = (const float4*)q_sh;
            float acc = 0.f;
            #pragma unroll
            for (int i = 0; i < 16; i++) {
                float4 x = vp[i];
                float4 qq = qp[i];
                acc += x.x * qq.x + x.y * qq.y + x.z * qq.z + x.w * qq.w;
            }
            sc = acc * 0.125f;
        }
        red[tid] = sc;
        __syncthreads();
        #pragma unroll
        for (int st = 256; st >= 32; st >>= 1) {
            if (tid < st) red[tid] = fmaxf(red[tid], red[tid + st]);
            __syncthreads();
        }
        if (tid < 32) {
            float m = red[tid];
            #pragma unroll
            for (int o = 16; o > 0; o >>= 1)
                m = fmaxf(m, __shfl_xor_sync(0xffffffff, m, o));
            if (tid == 0) s_mx = m;
        }
        __syncthreads();

        float e = (tid < nloc) ? expf(sc - s_mx) : 0.f;
        s_sh[tid] = e;
        red[tid]  = e;
        __syncthreads();
        #pragma unroll
        for (int st = 256; st >= 32; st >>= 1) {
            if (tid < st) red[tid] += red[tid + st];
            __syncthreads();
        }
        if (tid < 32) {
            float sm = red[tid];
            #pragma unroll
            for (int o = 16; o > 0; o >>= 1)
                sm += __shfl_xor_sync(0xffffffff, sm, o);
            if (tid == 0) s_sum = sm;
        }
        __syncthreads();

        {
            int g = tid >> 6, d = tid & 63;
            float acc = 0.f;
            for (int k = g; k < nloc; k += 8)
                acc += s_sh[k] * V[(long)(base + k) * TOKDIM + h * HDIM + d];
            red[tid] = acc;
        }
        __syncthreads();
        if (tid < HDIM) {
            float o = 0.f;
            #pragma unroll
            for (int gg = 0; gg < 8; gg++) o += red[gg * 64 + tid];
            atomicAdd(out + h * HDIM + tid, (s_sum > 0.f) ? (o / s_sum) : 0.f);
        }
    } else if (b < HEADS + P.nSmall * HEADS) {
        // ================= small cover-set node attention =================
        const int si    = (b - HEADS) >> 4;
        const int h     = (b - HEADS) & 15;
        const int depth = P.sdepth[si];
        const int K     = P.sK[si];

        if (tid < HDIM) q_sh[tid] = q[h * HDIM + tid];

        const float* Wd = W + (long)depth * HDIM * HDIM;
        #pragma unroll
        for (int i = tid; i < HDIM * HDIM; i += 512) {
            int d = i >> 6, e = i & 63;
            fW[e * 65 + d] = Wd[i];            // transposed, coalesced
        }
        if (tid == 0) {
            float t  = temp[depth];
            float sp = log1pf(expf(t));
            s_scale  = 1.0f / ((sp + 1e-6f) * 8.0f);
        }
        __syncthreads();

        if (tid < HDIM) {
            float acc = q_sh[tid];
            #pragma unroll
            for (int e = 0; e < HDIM; e++) acc += q_sh[e] * fW[e * 65 + tid];
            qd[tid] = acc;
        }
        __syncthreads();

        const float* fsrc = V + (long)P.soff[si] * TOKDIM;
        for (int i = tid; i < K * HDIM; i += 512) {
            int k = i >> 6, d = i & 63;
            fW[k * 65 + d] = fsrc[(long)k * TOKDIM + h * HDIM + d];
        }
        __syncthreads();

        float sc = -1e30f;
        if (tid < K) {
            float acc = 0.f;
            #pragma unroll
            for (int d = 0; d < HDIM; d++) acc += qd[d] * fW[tid * 65 + d];
            sc = acc * s_scale;
        }
        if (tid < 64) red[tid] = sc;
        __syncthreads();
        if (tid < 32) {
            float m = fmaxf(red[tid], red[tid + 32]);
            #pragma unroll
            for (int o = 16; o > 0; o >>= 1)
                m = fmaxf(m, __shfl_xor_sync(0xffffffff, m, o));
            if (tid == 0) s_mx = m;
        }
        __syncthreads();

        float e = (tid < K) ? expf(sc - s_mx) : 0.f;
        if (tid < 64) { s_sh[tid] = e; red[tid] = e; }
        __syncthreads();
        if (tid < 32) {
            float sm = red[tid] + red[tid + 32];
            #pragma unroll
            for (int o = 16; o > 0; o >>= 1)
                sm += __shfl_xor_sync(0xffffffff, sm, o);
            if (tid == 0) s_sum = sm;
        }
        __syncthreads();

        {
            int g = tid >> 6, d = tid & 63;
            float acc = 0.f;
            for (int k = g; k < K; k += 8) acc += s_sh[k] * fW[k * 65 + d];
            red[tid] = acc;
        }
        __syncthreads();
        if (tid < HDIM) {
            float o = 0.f;
            #pragma unroll
            for (int gg = 0; gg < 8; gg++) o += red[gg * 64 + tid];
            atomicAdd(out + h * HDIM + tid, (o / s_sum) * P.inv_n);
        }
    } else {
        // ================= big-node qd/scale precompute =================
        const int bi    = b - HEADS - P.nSmall * HEADS;
        const int depth = P.bdepth[bi];

        // full q [16][64] into smem
        for (int i = tid; i < HEADS * HDIM; i += 512) q_sh[i] = q[i];

        const float* Wd = W + (long)depth * HDIM * HDIM;
        #pragma unroll
        for (int i = tid; i < HDIM * HDIM; i += 512) {
            int d = i >> 6, e = i & 63;
            fW[e * 65 + d] = Wd[i];
        }
        if (tid == 0) {
            float t  = temp[depth];
            float sp = log1pf(expf(t));
            g_scale[bi] = 1.0f / ((sp + 1e-6f) * 8.0f);
        }
        __syncthreads();

        // qd[h][d] = q[h][d] + sum_e q[h][e] * W[d][e], 1024 outputs / 512 thr
        #pragma unroll
        for (int idx = tid; idx < HEADS * HDIM; idx += 512) {
            int h = idx >> 6, d = idx & 63;
            float acc = q_sh[h * HDIM + d];
            #pragma unroll
            for (int e = 0; e < HDIM; e++)
                acc += q_sh[h * HDIM + e] * fW[e * 65 + d];
            g_qd[bi * HEADS * HDIM + idx] = acc;
        }
    }
}

// ---- big-node attention: pure L2 (g_f + g_qd), K=64 always -----------------
// grid = nBig*16, block = 256.
__global__ void __launch_bounds__(256) big_kernel(
    IndepParams P, float* __restrict__ out)
{
    const int bi  = blockIdx.x >> 4;
    const int h   = blockIdx.x & 15;
    const int tid = threadIdx.x;

    __shared__ float f_sh[64 * 65];
    __shared__ float qd_sh[HDIM];
    __shared__ float s_sh[64];
    __shared__ float red[256];
    __shared__ float s_mx, s_sum;

    if (tid < HDIM) qd_sh[tid] = g_qd[bi * HEADS * HDIM + h * HDIM + tid];

    const float* fsrc = g_f + (long)bi * 64 * TOKDIM;
    for (int i = tid; i < 64 * HDIM; i += 256) {
        int k = i >> 6, d = i & 63;
        f_sh[k * 65 + d] = fsrc[(long)k * TOKDIM + h * HDIM + d];
    }
    __syncthreads();

    float sc = -1e30f;
    if (tid < 64) {
        float acc = 0.f;
        #pragma unroll
        for (int d = 0; d < HDIM; d++) acc += qd_sh[d] * f_sh[tid * 65 + d];
        sc = acc * g_scale[bi];
    }
    if (tid < 64) red[tid] = sc;
    __syncthreads();
    if (tid < 32) {
        float m = fmaxf(red[tid], red[tid + 32]);
        #pragma unroll
        for (int o = 16; o > 0; o >>= 1)
            m = fmaxf(m, __shfl_xor_sync(0xffffffff, m, o));
        if (tid == 0) s_mx = m;
    }
    __syncthreads();

    float e = (tid < 64) ? expf(sc - s_mx) : 0.f;
    if (tid < 64) { s_sh[tid] = e; red[tid] = e; }
    __syncthreads();
    if (tid < 32) {
        float sm = red[tid] + red[tid + 32];
        #pragma unroll
        for (int o = 16; o > 0; o >>= 1)
            sm += __shfl_xor_sync(0xffffffff, sm, o);
        if (tid == 0) s_sum = sm;
    }
    __syncthreads();

    {
        int g = tid >> 6, d = tid & 63;
        float acc = 0.f;
        for (int k = g; k < 64; k += 4) acc += s_sh[k] * f_sh[k * 65 + d];
        red[tid] = acc;
    }
    __syncthreads();
    if (tid < HDIM) {
        float o = (red[tid] + red[64 + tid]) + (red[128 + tid] + red[192 + tid]);
        atomicAdd(out + h * HDIM + tid, (o / s_sum) * P.inv_n);
    }
}

// ---------------------------------------------------------------------------
extern "C" void kernel_launch(void* const* d_in, const int* in_sizes, int n_in,
                              void* d_out, int out_size)
{
    const float* V    = (const float*)d_in[0];
    const float* q    = (const float*)d_in[1];
    const float* W    = (const float*)d_in[2];
    const float* temp = (const float*)d_in[3];

    const int pos = in_sizes[0] / TOKDIM;

    const int  LOG_N      = 17;
    const long LEAF_START = 1L << LOG_N;
    const long MAX_LEN    = 65536;

    PartParams  bp; bp.nBig = 0;
    IndepParams ip; ip.nSmall = 0; ip.nBig = 0;
    int nTotal = 0;

    auto addNode = [&](long idx) {
        int fl = 0; long t = idx;
        while (t > 1) { t >>= 1; fl++; }
        int depth = LOG_N - fl;
        long L = 1L << depth;
        long a = (idx << depth) - LEAF_START;
        nTotal++;
        if (L > 64) {
            int bi = bp.nBig++;
            bp.a[bi]   = (int)a;
            bp.C[bi]   = (int)(L / 64);
            bp.inv[bi] = 1.0f / (float)(L / 64);
            ip.bdepth[ip.nBig++] = depth;
        } else {
            int si = ip.nSmall++;
            ip.sdepth[si] = depth;
            ip.sK[si]     = (int)L;
            ip.soff[si]   = (int)a;
        }
    };

    long l = LEAF_START;
    long r = LEAF_START + (pos < MAX_LEN ? (long)pos : MAX_LEN);
    while (l < r) {
        if (l & 1) { addNode(l); l++; }
        if (r & 1) { r--; addNode(r); }
        l >>= 1; r >>= 1;
    }
    ip.inv_n = nTotal > 0 ? 1.0f / (float)nTotal : 0.f;

    bp.unitBase[0] = 0;
    for (int i = 0; i < bp.nBig; i++)
        bp.unitBase[i + 1] = bp.unitBase[i] + (long)bp.C[i] * 64;
    long U = bp.nBig ? bp.unitBase[bp.nBig] : 0;

    // lazy-init side stream + events (created on the uncaptured correctness call)
    static cudaStream_t s1 = nullptr;
    static cudaEvent_t  e1 = nullptr, e2 = nullptr;
    if (!s1) {
        cudaStreamCreateWithFlags(&s1, cudaStreamNonBlocking);
        cudaEventCreateWithFlags(&e1, cudaEventDisableTiming);
        cudaEventCreateWithFlags(&e2, cudaEventDisableTiming);
    }

    // fork
    cudaEventRecord(e1, 0);
    cudaStreamWaitEvent(s1, e1, 0);

    // side branch: zero out, independent attention + big-node prep
    cudaMemsetAsync(d_out, 0, (size_t)out_size * sizeof(float), s1);
    int gridA = HEADS + ip.nSmall * HEADS + ip.nBig;
    indep_kernel<<<gridA, 512, 0, s1>>>(V, q, W, temp, ip, pos, (float*)d_out);
    cudaEventRecord(e2, s1);

    // main branch: HBM stream
    if (bp.nBig > 0) {
        void* gf_ptr = nullptr;
        cudaGetSymbolAddress(&gf_ptr, g_f);
        cudaMemsetAsync(gf_ptr, 0, (size_t)bp.nBig * 64 * TOKDIM * sizeof(float));
        partial_kernel<<<GRID_P, 256>>>(V, bp, U);
    }

    // join, then big-node epilogue (needs g_f + g_qd)
    cudaStreamWaitEvent(0, e2, 0);
    if (bp.nBig > 0)
        big_kernel<<<bp.nBig * HEADS, 256>>>(ip, (float*)d_out);
}